// round 15
// baseline (speedup 1.0000x reference)
#include <cuda_runtime.h>
#include <math.h>

#define Bq 128
#define Uq 16
#define Dq 256
#define Nq 1024
#define Oq 256

__device__ float g_lr[Bq * Uq];

__device__ __forceinline__ float fast_tanh(float x) {
    float y;
    asm("tanh.approx.f32 %0, %1;" : "=f"(y) : "f"(x));
    return y;
}

__device__ __forceinline__ unsigned rna(float f) {
    unsigned r;
    asm("cvt.rna.tf32.f32 %0, %1;" : "=r"(r) : "f"(f));
    return r;
}

__device__ __forceinline__ void cp16(float* smem_dst, const float* gsrc) {
    unsigned s = (unsigned)__cvta_generic_to_shared(smem_dst);
    asm volatile("cp.async.cg.shared.global [%0], [%1], 16;\n" :: "r"(s), "l"(gsrc));
}
#define CP_COMMIT() asm volatile("cp.async.commit_group;\n" ::)
#define CP_WAIT1()  asm volatile("cp.async.wait_group 1;\n" ::)
#define CP_WAIT2()  asm volatile("cp.async.wait_group 2;\n" ::)

__device__ __forceinline__ void mma_tf32(float* c, const unsigned* a, const unsigned* b) {
    asm volatile(
        "mma.sync.aligned.m16n8k8.row.col.f32.tf32.tf32.f32 "
        "{%0,%1,%2,%3},{%4,%5,%6,%7},{%8,%9},{%0,%1,%2,%3};"
        : "+f"(c[0]), "+f"(c[1]), "+f"(c[2]), "+f"(c[3])
        : "r"(a[0]), "r"(a[1]), "r"(a[2]), "r"(a[3]), "r"(b[0]), "r"(b[1]));
}

// ---------------------------------------------------------------------------
// Kernel 1: lr = softmax_u( (X[b,u,:] . alr[u,:]) / T )
// ---------------------------------------------------------------------------
__global__ void lr_kernel(const float* __restrict__ X,
                          const float* __restrict__ alr,
                          const float* __restrict__ temp) {
    const int b    = blockIdx.x;
    const int u    = threadIdx.y;
    const int lane = threadIdx.x;

    const float4* xp = (const float4*)(X + ((size_t)b * Uq + u) * Dq);
    const float4* ap = (const float4*)(alr + (size_t)u * Dq);
    float4 x0 = xp[lane], x1 = xp[lane + 32];
    float4 a0 = ap[lane], a1 = ap[lane + 32];
    float sum = x0.x * a0.x + x0.y * a0.y + x0.z * a0.z + x0.w * a0.w +
                x1.x * a1.x + x1.y * a1.y + x1.z * a1.z + x1.w * a1.w;
#pragma unroll
    for (int o = 16; o; o >>= 1) sum += __shfl_xor_sync(0xffffffffu, sum, o);

    __shared__ float logits[Uq];
    if (lane == 0) logits[u] = sum / temp[0];
    __syncthreads();

    if (threadIdx.y == 0) {
        float l = logits[lane & 15];
        float m = l;
#pragma unroll
        for (int o = 8; o; o >>= 1) m = fmaxf(m, __shfl_xor_sync(0xffffffffu, m, o));
        float e = __expf(l - m);
        float s = e;
#pragma unroll
        for (int o = 8; o; o >>= 1) s += __shfl_xor_sync(0xffffffffu, s, o);
        if (lane < 16) g_lr[b * Uq + lane] = e / s;
    }
}

// ---------------------------------------------------------------------------
// Kernel 2: fused state update.  BM=128 BN=128 BK=32, 4-stage cp.async,
// 512 threads = 16 warps as 4(m) x 4(n); warp tile 32x32 = 2x4 m16n8k8.
// cvt.rna on fragments (sr folded before rounding for echo stages).
// ---------------------------------------------------------------------------
#define AS 36
#define BS 136
#define ST_STAGE_A (128 * AS)     // 4608 floats
#define ST_STAGE_B (32 * BS)      // 4352 floats
#define ST_STAGES 4

__global__ void __launch_bounds__(512, 1) state_kernel(
    const float* __restrict__ X, const float* __restrict__ state,
    const float* __restrict__ W, const float* __restrict__ Win,
    const float* __restrict__ bias, const float* __restrict__ sr,
    float* __restrict__ out_ns)
{
    extern __shared__ float smem[];
    float* sA = smem;                          // 4 * 4608
    float* sB = smem + ST_STAGES * ST_STAGE_A; // 4 * 4352

    const int u  = blockIdx.z;
    const int n0 = blockIdx.x * 128;
    const float srv = sr[u];

    const int t      = threadIdx.x;
    const int wid    = t >> 5;
    const int lane   = t & 31;
    const int gid    = lane >> 2;
    const int tig    = lane & 3;
    const int m_warp = (wid >> 2) * 32;   // 0,32,64,96
    const int n_warp = (wid & 3) * 32;    // 0..96

    // loaders (512 threads): A 128x32 (2 cp16/thread), B 32x128 (2 cp16/thread)
    const int la_m  = t >> 2;             // 0..127
    const int la_kg = (t & 3) << 3;       // 0,8,16,24
    const int lb_k  = t >> 4;             // 0..31
    const int lb_ng = (t & 15) << 3;      // 0..120

    float acc[2][4][4] = {};

#define ST_LOAD(KT, SI)                                                          \
    do {                                                                         \
        float* As_ = sA + (SI) * ST_STAGE_A;                                     \
        float* Bs_ = sB + (SI) * ST_STAGE_B;                                     \
        if ((KT) < Dq) {                                                         \
            const float* asrc = X + ((size_t)la_m * Uq + u) * Dq + (KT) + la_kg; \
            cp16(As_ + la_m * AS + la_kg,     asrc);                             \
            cp16(As_ + la_m * AS + la_kg + 4, asrc + 4);                         \
            const float* bsrc =                                                  \
                Win + ((size_t)u * Dq + (KT) + lb_k) * Nq + n0 + lb_ng;          \
            cp16(Bs_ + lb_k * BS + lb_ng,     bsrc);                             \
            cp16(Bs_ + lb_k * BS + lb_ng + 4, bsrc + 4);                         \
        } else {                                                                 \
            const float* asrc =                                                  \
                state + ((size_t)la_m * Uq + u) * Nq + (KT) - Dq + la_kg;        \
            cp16(As_ + la_m * AS + la_kg,     asrc);                             \
            cp16(As_ + la_m * AS + la_kg + 4, asrc + 4);                         \
            const float* bsrc =                                                  \
                W + ((size_t)u * Nq + (KT) - Dq + lb_k) * Nq + n0 + lb_ng;       \
            cp16(Bs_ + lb_k * BS + lb_ng,     bsrc);                             \
            cp16(Bs_ + lb_k * BS + lb_ng + 4, bsrc + 4);                         \
        }                                                                        \
    } while (0)

    ST_LOAD(0, 0);  CP_COMMIT();
    ST_LOAD(32, 1); CP_COMMIT();
    ST_LOAD(64, 2); CP_COMMIT();

    const int ITERS = (Dq + Nq) / 32;   // 40
    for (int i = 0; i < ITERS; i++) {
        CP_WAIT2();
        __syncthreads();
        const int pf = i + 3;
        if (pf < ITERS) ST_LOAD(pf * 32, pf & 3);
        CP_COMMIT();

        const int si = i & 3;
        const float* As_ = sA + si * ST_STAGE_A;
        const float* Bs_ = sB + si * ST_STAGE_B;
        const bool echo = (i * 32) >= Dq;

#pragma unroll
        for (int ks = 0; ks < 4; ks++) {
            const int kb = ks * 8;
            unsigned a[2][4], b[4][2];
#pragma unroll
            for (int mt = 0; mt < 2; mt++) {
                const int m = m_warp + mt * 16 + gid;
                float r0 = As_[(m) * AS + kb + tig];
                float r1 = As_[(m + 8) * AS + kb + tig];
                float r2 = As_[(m) * AS + kb + tig + 4];
                float r3 = As_[(m + 8) * AS + kb + tig + 4];
                if (echo) { r0 *= srv; r1 *= srv; r2 *= srv; r3 *= srv; }
                a[mt][0] = rna(r0); a[mt][1] = rna(r1);
                a[mt][2] = rna(r2); a[mt][3] = rna(r3);
            }
#pragma unroll
            for (int nt = 0; nt < 4; nt++) {
                const int n = n_warp + nt * 8 + gid;
                b[nt][0] = rna(Bs_[(kb + tig) * BS + n]);
                b[nt][1] = rna(Bs_[(kb + tig + 4) * BS + n]);
            }
#pragma unroll
            for (int mt = 0; mt < 2; mt++)
#pragma unroll
                for (int nt = 0; nt < 4; nt++)
                    mma_tf32(acc[mt][nt], a[mt], b[nt]);
        }
    }

    // epilogue: bias, tanh, lr-gated update
#pragma unroll
    for (int mt = 0; mt < 2; mt++) {
#pragma unroll
        for (int half = 0; half < 2; half++) {
            const int bb = m_warp + mt * 16 + gid + half * 8;
            const float lr  = g_lr[bb * Uq + u];
            const float oml = 1.f - lr;
            const float* srow = state  + ((size_t)bb * Uq + u) * Nq;
            float*       orow = out_ns + ((size_t)bb * Uq + u) * Nq;
#pragma unroll
            for (int nt = 0; nt < 4; nt++) {
                const int n = n0 + n_warp + nt * 8 + tig * 2;
#pragma unroll
                for (int j = 0; j < 2; j++) {
                    const float v = acc[mt][nt][half * 2 + j] + bias[u * Nq + n + j];
                    orow[n + j] = oml * srow[n + j] + lr * fast_tanh(v);
                }
            }
        }
    }
}

// ---------------------------------------------------------------------------
// Kernel 3: output = new_state @ Wout[u].  BM=64 BN=64 BK=32, 3 stages,
// 128 threads = 4 warps 2x2, warp tile 32x32.  rna on fragments.
// ---------------------------------------------------------------------------
#define OAS 36
#define OBS 72
#define O_STAGE_A (64 * OAS)
#define O_STAGE_B (32 * OBS)

__global__ void __launch_bounds__(128, 1) out_kernel(
    const float* __restrict__ ns, const float* __restrict__ Wout,
    float* __restrict__ out2)
{
    extern __shared__ float smem[];
    float* sA = smem;
    float* sB = smem + 3 * O_STAGE_A;

    const int u  = blockIdx.z;
    const int o0 = blockIdx.x * 64;
    const int b0 = blockIdx.y * 64;

    const int t      = threadIdx.x;
    const int wid    = t >> 5;
    const int lane   = t & 31;
    const int gid    = lane >> 2;
    const int tig    = lane & 3;
    const int m_warp = (wid >> 1) * 32;
    const int n_warp = (wid & 1) * 32;

    const int la_m = t >> 3;          // + i*16
    const int la_k = (t & 7) << 2;
    const int lb_k = t >> 4;          // + i*8
    const int lb_n = (t & 15) << 2;

    float acc[2][4][4] = {};

#define O_LOAD(KT, SI)                                                       \
    do {                                                                     \
        float* As_ = sA + (SI) * O_STAGE_A;                                  \
        float* Bs_ = sB + (SI) * O_STAGE_B;                                  \
        _Pragma("unroll")                                                    \
        for (int i_ = 0; i_ < 4; i_++) {                                     \
            int m_ = la_m + i_ * 16;                                         \
            cp16(As_ + m_ * OAS + la_k,                                      \
                 ns + ((size_t)(b0 + m_) * Uq + u) * Nq + (KT) + la_k);      \
        }                                                                    \
        _Pragma("unroll")                                                    \
        for (int i_ = 0; i_ < 4; i_++) {                                     \
            int k_ = lb_k + i_ * 8;                                          \
            cp16(Bs_ + k_ * OBS + lb_n,                                      \
                 Wout + ((size_t)u * Nq + (KT) + k_) * Oq + o0 + lb_n);      \
        }                                                                    \
    } while (0)

    O_LOAD(0, 0);  CP_COMMIT();
    O_LOAD(32, 1); CP_COMMIT();

    const int ITERS = Nq / 32;   // 32
    for (int i = 0; i < ITERS; i++) {
        CP_WAIT1();
        __syncthreads();
        const int pf = i + 2;
        if (pf < ITERS) O_LOAD(pf * 32, pf % 3);
        CP_COMMIT();

        const int si = i % 3;
        const float* As_ = sA + si * O_STAGE_A;
        const float* Bs_ = sB + si * O_STAGE_B;

#pragma unroll
        for (int ks = 0; ks < 4; ks++) {
            const int kb = ks * 8;
            unsigned a[2][4], b[4][2];
#pragma unroll
            for (int mt = 0; mt < 2; mt++) {
                const int m = m_warp + mt * 16 + gid;
                a[mt][0] = rna(As_[(m) * OAS + kb + tig]);
                a[mt][1] = rna(As_[(m + 8) * OAS + kb + tig]);
                a[mt][2] = rna(As_[(m) * OAS + kb + tig + 4]);
                a[mt][3] = rna(As_[(m + 8) * OAS + kb + tig + 4]);
            }
#pragma unroll
            for (int nt = 0; nt < 4; nt++) {
                const int n = n_warp + nt * 8 + gid;
                b[nt][0] = rna(Bs_[(kb + tig) * OBS + n]);
                b[nt][1] = rna(Bs_[(kb + tig + 4) * OBS + n]);
            }
#pragma unroll
            for (int mt = 0; mt < 2; mt++)
#pragma unroll
                for (int nt = 0; nt < 4; nt++)
                    mma_tf32(acc[mt][nt], a[mt], b[nt]);
        }
    }

#pragma unroll
    for (int mt = 0; mt < 2; mt++) {
#pragma unroll
        for (int half = 0; half < 2; half++) {
            const int bb = b0 + m_warp + mt * 16 + gid + half * 8;
            float* orow = out2 + ((size_t)bb * Uq + u) * Oq;
#pragma unroll
            for (int nt = 0; nt < 4; nt++) {
                const int n = o0 + n_warp + nt * 8 + tig * 2;
                orow[n + 0] = acc[mt][nt][half * 2 + 0];
                orow[n + 1] = acc[mt][nt][half * 2 + 1];
            }
        }
    }
}

// ---------------------------------------------------------------------------
extern "C" void kernel_launch(void* const* d_in, const int* in_sizes, int n_in,
                              void* d_out, int out_size) {
    const float* X     = (const float*)d_in[0];
    const float* state = (const float*)d_in[1];
    const float* W     = (const float*)d_in[2];
    const float* Win   = (const float*)d_in[3];
    const float* bias  = (const float*)d_in[4];
    const float* Wout  = (const float*)d_in[5];
    const float* sr    = (const float*)d_in[6];
    const float* alr   = (const float*)d_in[7];
    const float* temp  = (const float*)d_in[8];

    float* out_ns = (float*)d_out;                  // (B,U,N)
    float* out_o  = out_ns + (size_t)Bq * Uq * Nq;  // (B,U,O)

    const int st_smem = ST_STAGES * (ST_STAGE_A + ST_STAGE_B) * (int)sizeof(float); // 143360
    const int o_smem  = 3 * (O_STAGE_A + O_STAGE_B) * (int)sizeof(float);           //  55296
    cudaFuncSetAttribute(state_kernel, cudaFuncAttributeMaxDynamicSharedMemorySize, st_smem);
    cudaFuncSetAttribute(out_kernel,   cudaFuncAttributeMaxDynamicSharedMemorySize, o_smem);

    lr_kernel<<<Bq, dim3(32, Uq)>>>(X, alr, temp);
    state_kernel<<<dim3(Nq / 128, 1, Uq), 512, st_smem>>>(X, state, W, Win, bias, sr, out_ns);
    out_kernel<<<dim3(Oq / 64, Bq / 64, Uq), 128, o_smem>>>(out_ns, Wout, out_o);
}